// round 15
// baseline (speedup 1.0000x reference)
#include <cuda_runtime.h>

// Scalar DCP reduction, single kernel, last-block finalize.
// result = sum_{b,r,c} w(r)*w(c)*|min over 3 channels of x[b,ch,r,c]|
// w = 2 at index 0 or 1023, else 3. Zero padding contributes 0.
//
// Combines the two empirically-best mechanics:
//  - R8: per-thread distance-1 prefetch.global.L2 of everything + .cs
//    demand policy (software pipeline into L2; best warm time)
//  - R10: 256-bit v4.b64 demand loads, one thread per 8 floats (half the
//    load instructions / index math; best cold time)

#define TPB   512
#define GRID  592u              // 148 SMs * 4 blocks -> exactly one wave
#define N8    2097152u          // 16*1024*128 vec8 positions
#define CH8   131072u           // vec8 per channel image (2^17)
#define OFF8M 0x1FFFFu          // offset-within-image mask (vec8 units)

__device__ double   g_sum;      // zero-init; reset by last block each run
__device__ unsigned g_ticket;   // zero-init; wraps back to 0 each run

struct V8 { float f[8]; };

__device__ __forceinline__ V8 ld_cs8(const void* p) {
    unsigned long long u0, u1, u2, u3;
    asm volatile("ld.global.cs.v4.b64 {%0,%1,%2,%3}, [%4];"
                 : "=l"(u0), "=l"(u1), "=l"(u2), "=l"(u3) : "l"(p));
    V8 v;
    v.f[0] = __uint_as_float((unsigned)u0);  v.f[1] = __uint_as_float((unsigned)(u0 >> 32));
    v.f[2] = __uint_as_float((unsigned)u1);  v.f[3] = __uint_as_float((unsigned)(u1 >> 32));
    v.f[4] = __uint_as_float((unsigned)u2);  v.f[5] = __uint_as_float((unsigned)(u2 >> 32));
    v.f[6] = __uint_as_float((unsigned)u3);  v.f[7] = __uint_as_float((unsigned)(u3 >> 32));
    return v;
}

__global__ __launch_bounds__(TPB, 4) void dcp_kernel(const float* __restrict__ x,
                                                     float* __restrict__ out) {
    const unsigned stride = GRID * TPB;
    float tsum = 0.f;

    #pragma unroll 1
    for (unsigned i = blockIdx.x * TPB + threadIdx.x; i < N8; i += stride) {
        unsigned off = i & OFF8M;
        unsigned c8  = i & 127u;
        unsigned r   = (i >> 7) & 1023u;
        unsigned b   = i >> 17;

        const float* base = x + ((unsigned long long)(b * 3u) << 20)
                              + ((unsigned long long)off << 3);

        // distance-1 prefetch of next iteration's three lines (R8 mechanic)
        unsigned i2 = i + stride;
        if (i2 < N8) {
            const float* q = x + ((unsigned long long)((i2 >> 17) * 3u) << 20)
                               + ((unsigned long long)(i2 & OFF8M) << 3);
            asm volatile("prefetch.global.L2 [%0];" :: "l"(q));
            asm volatile("prefetch.global.L2 [%0];" :: "l"(q + (1u << 20)));
            asm volatile("prefetch.global.L2 [%0];" :: "l"(q + (2u << 20)));
        }

        float m[8];
        V8 a0 = ld_cs8(base);
        V8 a1 = ld_cs8(base + (1u << 20));
        #pragma unroll
        for (int j = 0; j < 8; j++) m[j] = fminf(a0.f[j], a1.f[j]);
        V8 a2 = ld_cs8(base + (2u << 20));
        #pragma unroll
        for (int j = 0; j < 8; j++) m[j] = fabsf(fminf(m[j], a2.f[j]));

        float wr = (r == 0u || r == 1023u) ? 2.f : 3.f;
        float w0 = (c8 == 0u)   ? 2.f : 3.f;   // col 0 in lane 0
        float w7 = (c8 == 127u) ? 2.f : 3.f;   // col 1023 in lane 7

        float mid = ((m[1] + m[2]) + (m[3] + m[4])) + (m[5] + m[6]);
        float s = fmaf(w0, m[0], fmaf(3.f, mid, w7 * m[7]));
        tsum = fmaf(wr, s, tsum);
    }

    // intra-block reduction
    #pragma unroll
    for (int ofs = 16; ofs > 0; ofs >>= 1)
        tsum += __shfl_xor_sync(0xFFFFFFFFu, tsum, ofs);

    __shared__ float warp_sums[TPB / 32];
    int lane = threadIdx.x & 31;
    int wid  = threadIdx.x >> 5;
    if (lane == 0) warp_sums[wid] = tsum;
    __syncthreads();

    if (threadIdx.x == 0) {
        float v = 0.f;
        #pragma unroll
        for (int w = 0; w < TPB / 32; w++) v += warp_sums[w];

        atomicAdd(&g_sum, (double)v);
        __threadfence();
        unsigned old = atomicInc(&g_ticket, GRID - 1u);   // wraps -> self-reset
        if (old == GRID - 1u) {
            double tot = atomicAdd(&g_sum, 0.0);          // coherent read
            out[0] = (float)tot;
            g_sum = 0.0;            // reset for next graph replay
            __threadfence();
        }
    }
}

extern "C" void kernel_launch(void* const* d_in, const int* in_sizes, int n_in,
                              void* d_out, int out_size) {
    const float* x = (const float*)d_in[0];
    dcp_kernel<<<GRID, TPB>>>(x, (float*)d_out);
}

// round 16
// speedup vs baseline: 1.2696x; 1.2696x over previous
#include <cuda_runtime.h>

// Scalar DCP reduction, single kernel, last-block finalize.
// result = sum_{b,r,c} w(r)*w(c)*|min over 3 channels of x[b,ch,r,c]|
// w = 2 at index 0 or 1023, else 3. Zero padding contributes 0.
//
// R8 configuration (empirical winner: 128-bit __ldcs demand loads +
// per-thread prefetch.global.L2 of everything, 512thr x 592blk, one wave)
// with the prefetch distance raised from 1 to 2 grid-stride iterations
// (~4.6us lead instead of ~2.3us) at identical instruction cost.

#define TPB   512
#define GRID  592u              // 148 SMs * 4 blocks -> exactly one wave
#define N4    4194304u          // 16*1024*256 vec4 positions
#define CH4   262144u           // 2^18 float4 per channel
#define OFFM  0x3FFFFu          // offset-within-image mask (float4 units)

__device__ double   g_sum;      // zero-init; reset by last block each run
__device__ unsigned g_ticket;   // zero-init; wraps back to 0 each run

__global__ __launch_bounds__(TPB, 4) void dcp_kernel(const float* __restrict__ x,
                                                     float* __restrict__ out) {
    const unsigned stride = GRID * TPB;
    const float4* x4 = (const float4*)x;
    float tsum = 0.f;

    #pragma unroll 1
    for (unsigned i = blockIdx.x * TPB + threadIdx.x; i < N4; i += stride) {
        unsigned c4 = i & 255u;
        unsigned r  = (i >> 8) & 1023u;
        unsigned b  = i >> 18;

        const float4* p = x4 + (b * 3u << 18) + (i & OFFM);

        // prefetch TWO iterations ahead (same cost, double the lead time)
        unsigned i2 = i + 2u * stride;
        if (i2 < N4) {
            const float4* q = x4 + ((i2 >> 18) * 3u << 18) + (i2 & OFFM);
            asm volatile("prefetch.global.L2 [%0];" :: "l"(q));
            asm volatile("prefetch.global.L2 [%0];" :: "l"(q + CH4));
            asm volatile("prefetch.global.L2 [%0];" :: "l"(q + 2u * CH4));
        }

        float4 a0 = __ldcs(p);
        float4 a1 = __ldcs(p + CH4);
        float4 a2 = __ldcs(p + 2u * CH4);

        float m0 = fabsf(fminf(fminf(a0.x, a1.x), a2.x));
        float m1 = fabsf(fminf(fminf(a0.y, a1.y), a2.y));
        float m2 = fabsf(fminf(fminf(a0.z, a1.z), a2.z));
        float m3 = fabsf(fminf(fminf(a0.w, a1.w), a2.w));

        float wr = (r == 0u || r == 1023u) ? 2.f : 3.f;
        float w0 = (c4 == 0u)   ? 2.f : 3.f;   // col 0 lives in first vec
        float w3 = (c4 == 255u) ? 2.f : 3.f;   // col 1023 in last vec

        float s = fmaf(w0, m0, fmaf(3.f, m1 + m2, w3 * m3));
        tsum = fmaf(wr, s, tsum);
    }

    // intra-block reduction
    #pragma unroll
    for (int ofs = 16; ofs > 0; ofs >>= 1)
        tsum += __shfl_xor_sync(0xFFFFFFFFu, tsum, ofs);

    __shared__ float warp_sums[TPB / 32];
    int lane = threadIdx.x & 31;
    int wid  = threadIdx.x >> 5;
    if (lane == 0) warp_sums[wid] = tsum;
    __syncthreads();

    if (threadIdx.x == 0) {
        float v = 0.f;
        #pragma unroll
        for (int w = 0; w < TPB / 32; w++) v += warp_sums[w];

        atomicAdd(&g_sum, (double)v);
        __threadfence();
        unsigned old = atomicInc(&g_ticket, GRID - 1u);   // wraps -> self-reset
        if (old == GRID - 1u) {
            double tot = atomicAdd(&g_sum, 0.0);          // coherent read
            out[0] = (float)tot;
            g_sum = 0.0;            // reset for next graph replay
            __threadfence();
        }
    }
}

extern "C" void kernel_launch(void* const* d_in, const int* in_sizes, int n_in,
                              void* d_out, int out_size) {
    const float* x = (const float*)d_in[0];
    dcp_kernel<<<GRID, TPB>>>(x, (float*)d_out);
}

// round 17
// speedup vs baseline: 1.3645x; 1.0748x over previous
#include <cuda_runtime.h>

// Scalar DCP reduction, single kernel, last-block finalize.
// result = sum_{b,r,c} w(r)*w(c)*|min over 3 channels of x[b,ch,r,c]|
// w = 2 at index 0 or 1023, else 3. (Derived from pad + 3x3 window sum:
// each pixel is counted once per covering window; zero padding contributes
// |min(0,0,0)| = 0.)
//
// Final configuration (empirical optimum over 10 single-variable probes):
//  - grid-stride, 512 thr x 592 blocks (4/SM, 2048 thr/SM, one exact wave)
//  - demand loads: 128-bit __ldcs (evict-first fills; hits don't demote)
//  - per-thread distance-1 prefetch.global.L2 of ALL of next iteration's
//    lines: a zero-register, zero-scoreboard software pipeline into L2 that
//    converts demand DRAM misses into L2 hits (and incidentally keeps much
//    of the input warm across graph replays)
//  - finalize: one atomicAdd(double) per block + self-resetting ticket
//    (graph-replay safe, deterministic)
// Measured: 27.4us = 7.35 TB/s effective (~92% of 8TB/s HBM spec).

#define TPB   512
#define GRID  592u              // 148 SMs * 4 blocks -> exactly one wave
#define N4    4194304u          // 16*1024*256 vec4 positions
#define CH4   262144u           // 2^18 float4 per channel
#define OFFM  0x3FFFFu          // offset-within-image mask (float4 units)

__device__ double   g_sum;      // zero-init; reset by last block each run
__device__ unsigned g_ticket;   // zero-init; wraps back to 0 each run

__global__ __launch_bounds__(TPB, 4) void dcp_kernel(const float* __restrict__ x,
                                                     float* __restrict__ out) {
    const unsigned stride = GRID * TPB;
    const float4* x4 = (const float4*)x;
    float tsum = 0.f;

    #pragma unroll 1
    for (unsigned i = blockIdx.x * TPB + threadIdx.x; i < N4; i += stride) {
        unsigned c4 = i & 255u;
        unsigned r  = (i >> 8) & 1023u;
        unsigned b  = i >> 18;

        const float4* p = x4 + (b * 3u << 18) + (i & OFFM);

        // prefetch next iteration's three lines into L2 (no reg, no SB)
        unsigned i2 = i + stride;
        if (i2 < N4) {
            const float4* q = x4 + ((i2 >> 18) * 3u << 18) + (i2 & OFFM);
            asm volatile("prefetch.global.L2 [%0];" :: "l"(q));
            asm volatile("prefetch.global.L2 [%0];" :: "l"(q + CH4));
            asm volatile("prefetch.global.L2 [%0];" :: "l"(q + 2u * CH4));
        }

        float4 a0 = __ldcs(p);
        float4 a1 = __ldcs(p + CH4);
        float4 a2 = __ldcs(p + 2u * CH4);

        float m0 = fabsf(fminf(fminf(a0.x, a1.x), a2.x));
        float m1 = fabsf(fminf(fminf(a0.y, a1.y), a2.y));
        float m2 = fabsf(fminf(fminf(a0.z, a1.z), a2.z));
        float m3 = fabsf(fminf(fminf(a0.w, a1.w), a2.w));

        float wr = (r == 0u || r == 1023u) ? 2.f : 3.f;
        float w0 = (c4 == 0u)   ? 2.f : 3.f;   // col 0 lives in first vec
        float w3 = (c4 == 255u) ? 2.f : 3.f;   // col 1023 in last vec

        float s = fmaf(w0, m0, fmaf(3.f, m1 + m2, w3 * m3));
        tsum = fmaf(wr, s, tsum);
    }

    // intra-block reduction
    #pragma unroll
    for (int ofs = 16; ofs > 0; ofs >>= 1)
        tsum += __shfl_xor_sync(0xFFFFFFFFu, tsum, ofs);

    __shared__ float warp_sums[TPB / 32];
    int lane = threadIdx.x & 31;
    int wid  = threadIdx.x >> 5;
    if (lane == 0) warp_sums[wid] = tsum;
    __syncthreads();

    if (threadIdx.x == 0) {
        float v = 0.f;
        #pragma unroll
        for (int w = 0; w < TPB / 32; w++) v += warp_sums[w];

        atomicAdd(&g_sum, (double)v);
        __threadfence();
        unsigned old = atomicInc(&g_ticket, GRID - 1u);   // wraps -> self-reset
        if (old == GRID - 1u) {
            double tot = atomicAdd(&g_sum, 0.0);          // coherent read
            out[0] = (float)tot;
            g_sum = 0.0;            // reset for next graph replay
            __threadfence();
        }
    }
}

extern "C" void kernel_launch(void* const* d_in, const int* in_sizes, int n_in,
                              void* d_out, int out_size) {
    const float* x = (const float*)d_in[0];
    dcp_kernel<<<GRID, TPB>>>(x, (float*)d_out);
}